// round 5
// baseline (speedup 1.0000x reference)
#include <cuda_runtime.h>

// VDDecoder: 3-layer LSTM stack (H=2,2,1), locked dropout between layers.
// Warp-specialized: per 32 batch elements, warp A computes layer1 + layer3 +
// output store, warp B computes layer2. 1-step pipeline stagger per hop;
// h1/h2 exchanged through double-buffered smem with one __syncthreads per
// timestep. Dropout masks folded into consumer weight columns.
// Activations: single-MUFU tanh.approx; sigmoid rows pre-scaled by 0.5 so
// sigmoid(g) = 0.5*tanh(g') + 0.5.

__device__ __forceinline__ float ftanh(float x) {
    float r;
    asm("tanh.approx.f32 %0, %1;" : "=f"(r) : "f"(x));
    return r;
}
__device__ __forceinline__ float fsigp(float g) {   // g built with 0.5-scaled weights
    return fmaf(ftanh(g), 0.5f, 0.5f);
}

extern "C" __global__ void __launch_bounds__(64)
vdlstm_ws_kernel(const float* __restrict__ x,
                 const float* __restrict__ W1ih, const float* __restrict__ W1hh,
                 const float* __restrict__ b1,   const float* __restrict__ m1,
                 const float* __restrict__ W2ih, const float* __restrict__ W2hh,
                 const float* __restrict__ b2,   const float* __restrict__ m2,
                 const float* __restrict__ W3ih, const float* __restrict__ W3hh,
                 const float* __restrict__ b3,   const float* __restrict__ m3,
                 float* __restrict__ out, int T, int B)
{
    __shared__ float2 sh1[2][32];   // raw h1 per element, double-buffered
    __shared__ float2 sh2[2][32];   // raw h2 per element, double-buffered

    const int lane = threadIdx.x & 31;
    const bool wA  = threadIdx.x < 32;
    const int b    = blockIdx.x * 32 + lane;

    // ---- role-specific weight registers ----
    float w1i[8], w1h[16], bb1[8];          // A: layer1 (0.5-scaled sigmoid rows)
    float w3i[8], w3h[4], bb3[4], m30 = 0.f;// A: layer3 (m2 folded into w3i)
    float w2i[16], w2h[16], bb2[8];         // B: layer2 (m1 folded into w2i)

    if (wA) {
#pragma unroll
        for (int k = 0; k < 8; k++) {
            float s = (k == 4 || k == 5) ? 1.0f : 0.5f;
            w1i[k]         = W1ih[k] * s;
            w1h[2 * k]     = W1hh[2 * k] * s;
            w1h[2 * k + 1] = W1hh[2 * k + 1] * s;
            bb1[k]         = b1[k] * s;
        }
        float m20 = m2[2 * b + 0], m21 = m2[2 * b + 1];
#pragma unroll
        for (int k = 0; k < 4; k++) {
            float s = (k == 2) ? 1.0f : 0.5f;
            w3i[2 * k]     = W3ih[2 * k] * s * m20;
            w3i[2 * k + 1] = W3ih[2 * k + 1] * s * m21;
            w3h[k]         = W3hh[k] * s;
            bb3[k]         = b3[k] * s;
        }
        m30 = m3[b];
    } else {
        float m10 = m1[2 * b + 0], m11 = m1[2 * b + 1];
#pragma unroll
        for (int k = 0; k < 8; k++) {
            float s = (k == 4 || k == 5) ? 1.0f : 0.5f;
            w2i[2 * k]     = W2ih[2 * k] * s * m10;
            w2i[2 * k + 1] = W2ih[2 * k + 1] * s * m11;
            w2h[2 * k]     = W2hh[2 * k] * s;
            w2h[2 * k + 1] = W2hh[2 * k + 1] * s;
            bb2[k]         = b2[k] * s;
        }
    }

    // ---- states ----
    float h10 = 0.f, h11 = 0.f, c10 = 0.f, c11 = 0.f;   // A
    float h3 = 0.f,  c3 = 0.f;                          // A
    float h20 = 0.f, h21 = 0.f, c20 = 0.f, c21 = 0.f;   // B

    auto step1 = [&](float xt) {   // raw h1 (no mask)
        float g0 = fmaf(xt, w1i[0], fmaf(h10, w1h[0],  fmaf(h11, w1h[1],  bb1[0])));
        float g1 = fmaf(xt, w1i[1], fmaf(h10, w1h[2],  fmaf(h11, w1h[3],  bb1[1])));
        float g2 = fmaf(xt, w1i[2], fmaf(h10, w1h[4],  fmaf(h11, w1h[5],  bb1[2])));
        float g3 = fmaf(xt, w1i[3], fmaf(h10, w1h[6],  fmaf(h11, w1h[7],  bb1[3])));
        float g4 = fmaf(xt, w1i[4], fmaf(h10, w1h[8],  fmaf(h11, w1h[9],  bb1[4])));
        float g5 = fmaf(xt, w1i[5], fmaf(h10, w1h[10], fmaf(h11, w1h[11], bb1[5])));
        float g6 = fmaf(xt, w1i[6], fmaf(h10, w1h[12], fmaf(h11, w1h[13], bb1[6])));
        float g7 = fmaf(xt, w1i[7], fmaf(h10, w1h[14], fmaf(h11, w1h[15], bb1[7])));
        float i0 = fsigp(g0), i1 = fsigp(g1);
        float f0 = fsigp(g2), f1 = fsigp(g3);
        float t0 = ftanh(g4), t1 = ftanh(g5);
        float o0 = fsigp(g6), o1 = fsigp(g7);
        c10 = fmaf(f0, c10, i0 * t0);
        c11 = fmaf(f1, c11, i1 * t1);
        h10 = o0 * ftanh(c10);
        h11 = o1 * ftanh(c11);
    };

    auto step2 = [&](float a0, float a1) {   // a = raw h1 (m1 folded in w2i)
        float g0 = fmaf(a0, w2i[0],  fmaf(a1, w2i[1],  fmaf(h20, w2h[0],  fmaf(h21, w2h[1],  bb2[0]))));
        float g1 = fmaf(a0, w2i[2],  fmaf(a1, w2i[3],  fmaf(h20, w2h[2],  fmaf(h21, w2h[3],  bb2[1]))));
        float g2 = fmaf(a0, w2i[4],  fmaf(a1, w2i[5],  fmaf(h20, w2h[4],  fmaf(h21, w2h[5],  bb2[2]))));
        float g3 = fmaf(a0, w2i[6],  fmaf(a1, w2i[7],  fmaf(h20, w2h[6],  fmaf(h21, w2h[7],  bb2[3]))));
        float g4 = fmaf(a0, w2i[8],  fmaf(a1, w2i[9],  fmaf(h20, w2h[8],  fmaf(h21, w2h[9],  bb2[4]))));
        float g5 = fmaf(a0, w2i[10], fmaf(a1, w2i[11], fmaf(h20, w2h[10], fmaf(h21, w2h[11], bb2[5]))));
        float g6 = fmaf(a0, w2i[12], fmaf(a1, w2i[13], fmaf(h20, w2h[12], fmaf(h21, w2h[13], bb2[6]))));
        float g7 = fmaf(a0, w2i[14], fmaf(a1, w2i[15], fmaf(h20, w2h[14], fmaf(h21, w2h[15], bb2[7]))));
        float i0 = fsigp(g0), i1 = fsigp(g1);
        float f0 = fsigp(g2), f1 = fsigp(g3);
        float t0 = ftanh(g4), t1 = ftanh(g5);
        float o0 = fsigp(g6), o1 = fsigp(g7);
        c20 = fmaf(f0, c20, i0 * t0);
        c21 = fmaf(f1, c21, i1 * t1);
        h20 = o0 * ftanh(c20);
        h21 = o1 * ftanh(c21);
    };

    auto step3 = [&](float a0, float a1) -> float {   // a = raw h2 (m2 folded in w3i)
        float g0 = fmaf(a0, w3i[0], fmaf(a1, w3i[1], fmaf(h3, w3h[0], bb3[0])));
        float g1 = fmaf(a0, w3i[2], fmaf(a1, w3i[3], fmaf(h3, w3h[1], bb3[1])));
        float g2 = fmaf(a0, w3i[4], fmaf(a1, w3i[5], fmaf(h3, w3h[2], bb3[2])));
        float g3 = fmaf(a0, w3i[6], fmaf(a1, w3i[7], fmaf(h3, w3h[3], bb3[3])));
        float ig = fsigp(g0), fg = fsigp(g1), gg = ftanh(g2), og = fsigp(g3);
        c3 = fmaf(fg, c3, ig * gg);
        h3 = og * ftanh(c3);
        return h3 * m30;
    };

    const float* xp = x + b;
    float* op = out + b;
    const long long Bs = (long long)B;

    // ---- prologue ----
    // u = 0: A computes h1(0) -> sh1[0]
    if (wA) {
        step1(xp[0]);
        sh1[0][lane] = make_float2(h10, h11);
    }
    __syncthreads();
    // u = 1: A computes h1(1) -> sh1[1]; B computes h2(0) -> sh2[0]
    if (wA) {
        step1(xp[Bs]);
        sh1[1][lane] = make_float2(h10, h11);
    } else {
        float2 a = sh1[0][lane];
        step2(a.x, a.y);
        sh2[0][lane] = make_float2(h20, h21);
    }
    __syncthreads();

    // ---- steady state: u = 2 .. T-1 ----
    // A: out(u-2) from sh2[u&1]; h1(u) -> sh1[u&1]
    // B: h2(u-1) from sh1[(u^1)&1] -> sh2[(u^1)&1]
    float xa = 0.f, xb = 0.f, xc = 0.f, xd = 0.f;
    if (wA) { xa = xp[2 * Bs]; xb = xp[3 * Bs]; xc = xp[4 * Bs]; xd = xp[5 * Bs]; }

#define WS_ITER(XREG, OFF)                                                     \
    {                                                                          \
        const int uu = u + (OFF);                                              \
        if (wA) {                                                              \
            float2 p2 = sh2[uu & 1][lane];                                     \
            op[(long long)(uu - 2) * Bs] = step3(p2.x, p2.y);                  \
            float nx = ((uu + 4) < T) ? xp[(long long)(uu + 4) * Bs] : 0.f;    \
            step1(XREG);                                                       \
            sh1[uu & 1][lane] = make_float2(h10, h11);                         \
            XREG = nx;                                                         \
        } else {                                                               \
            float2 p1 = sh1[(uu & 1) ^ 1][lane];                               \
            step2(p1.x, p1.y);                                                 \
            sh2[(uu & 1) ^ 1][lane] = make_float2(h20, h21);                   \
        }                                                                      \
        __syncthreads();                                                       \
    }

    int u = 2;
    for (; u + 3 < T; u += 4) {
        WS_ITER(xa, 0)
        WS_ITER(xb, 1)
        WS_ITER(xc, 2)
        WS_ITER(xd, 3)
    }
    for (; u < T; ++u) {
        if (wA) {
            float2 p2 = sh2[u & 1][lane];
            op[(long long)(u - 2) * Bs] = step3(p2.x, p2.y);
            step1(xa);
            sh1[u & 1][lane] = make_float2(h10, h11);
            xa = xb; xb = xc; xc = xd;
        } else {
            float2 p1 = sh1[(u & 1) ^ 1][lane];
            step2(p1.x, p1.y);
            sh2[(u & 1) ^ 1][lane] = make_float2(h20, h21);
        }
        __syncthreads();
    }
#undef WS_ITER

    // ---- epilogue ----
    // u = T: A emits out(T-2); B computes h2(T-1) -> sh2[(T^1)&1]
    if (wA) {
        float2 p2 = sh2[T & 1][lane];
        op[(long long)(T - 2) * Bs] = step3(p2.x, p2.y);
    } else {
        float2 p1 = sh1[(T & 1) ^ 1][lane];
        step2(p1.x, p1.y);
        sh2[(T & 1) ^ 1][lane] = make_float2(h20, h21);
    }
    __syncthreads();
    // u = T+1: A emits out(T-1)
    if (wA) {
        float2 p2 = sh2[(T & 1) ^ 1][lane];
        op[(long long)(T - 1) * Bs] = step3(p2.x, p2.y);
    }
}

extern "C" void kernel_launch(void* const* d_in, const int* in_sizes, int n_in,
                              void* d_out, int out_size)
{
    const float* x    = (const float*)d_in[0];
    const float* W1ih = (const float*)d_in[1];
    const float* W1hh = (const float*)d_in[2];
    const float* b1   = (const float*)d_in[3];
    const float* m1   = (const float*)d_in[4];
    const float* W2ih = (const float*)d_in[5];
    const float* W2hh = (const float*)d_in[6];
    const float* b2   = (const float*)d_in[7];
    const float* m2   = (const float*)d_in[8];
    const float* W3ih = (const float*)d_in[9];
    const float* W3hh = (const float*)d_in[10];
    const float* b3   = (const float*)d_in[11];
    const float* m3   = (const float*)d_in[12];

    int B = in_sizes[12];            // m3 is [B]
    int T = in_sizes[0] / B;         // x is [T, B, 1]

    int blocks = (B + 31) / 32;      // 32 elements per block, 2 warps each
    vdlstm_ws_kernel<<<blocks, 64>>>(x, W1ih, W1hh, b1, m1,
                                     W2ih, W2hh, b2, m2,
                                     W3ih, W3hh, b3, m3,
                                     (float*)d_out, T, B);
}

// round 6
// speedup vs baseline: 2.3901x; 2.3901x over previous
#include <cuda_runtime.h>

// VDDecoder: 3-layer LSTM stack (H=2,2,1), locked dropout between layers.
// One thread per batch element; layers software-pipelined with 1-step stagger.
// Gate/cell arithmetic vectorized with packed fp32 pairs (fma.rn.f32x2 /
// mul.rn.f32x2, sm_100+), full fp32 precision. Activations: single-MUFU
// tanh.approx; sigmoid rows pre-scaled by 0.5 so sigmoid(g)=0.5*tanh(g')+0.5.
// Dropout masks m1/m2 folded into consumer weight columns; m3 applied at end.

typedef unsigned long long u64;

__device__ __forceinline__ float ftanh(float x) {
    float r; asm("tanh.approx.f32 %0, %1;" : "=f"(r) : "f"(x)); return r;
}
__device__ __forceinline__ u64 fpack(float lo, float hi) {
    u64 d; asm("mov.b64 %0, {%1, %2};" : "=l"(d) : "f"(lo), "f"(hi)); return d;
}
__device__ __forceinline__ void funpack(u64 v, float& lo, float& hi) {
    asm("mov.b64 {%0, %1}, %2;" : "=f"(lo), "=f"(hi) : "l"(v));
}
__device__ __forceinline__ u64 ffma2(u64 a, u64 b, u64 c) {
    u64 d; asm("fma.rn.f32x2 %0, %1, %2, %3;" : "=l"(d) : "l"(a), "l"(b), "l"(c)); return d;
}
__device__ __forceinline__ u64 fmul2(u64 a, u64 b) {
    u64 d; asm("mul.rn.f32x2 %0, %1, %2;" : "=l"(d) : "l"(a), "l"(b)); return d;
}

extern "C" __global__ void __launch_bounds__(64, 1)
vdlstm_v2_kernel(const float* __restrict__ x,
                 const float* __restrict__ W1ih, const float* __restrict__ W1hh,
                 const float* __restrict__ b1,   const float* __restrict__ m1,
                 const float* __restrict__ W2ih, const float* __restrict__ W2hh,
                 const float* __restrict__ b2,   const float* __restrict__ m2,
                 const float* __restrict__ W3ih, const float* __restrict__ W3hh,
                 const float* __restrict__ b3,   const float* __restrict__ m3,
                 float* __restrict__ out, int T, int B)
{
    int b = blockIdx.x * blockDim.x + threadIdx.x;
    if (b >= B) return;

    const float m10 = m1[2 * b + 0], m11 = m1[2 * b + 1];
    const float m20 = m2[2 * b + 0], m21 = m2[2 * b + 1];
    const float m30 = m3[b];

    const u64 H2 = fpack(0.5f, 0.5f);

    // ---- packed weights; gate-pair p covers rows (2p, 2p+1) ----
    // torch order: p=0 -> i, p=1 -> f, p=2 -> g (tanh, unscaled), p=3 -> o
    u64 P1wi[4], P1wh0[4], P1wh1[4], P1b[4];
#pragma unroll
    for (int p = 0; p < 4; p++) {
        float s = (p == 2) ? 1.0f : 0.5f;
        int r0 = 2 * p, r1 = 2 * p + 1;
        P1wi[p]  = fpack(W1ih[r0] * s,          W1ih[r1] * s);
        P1wh0[p] = fpack(W1hh[2 * r0 + 0] * s,  W1hh[2 * r1 + 0] * s);
        P1wh1[p] = fpack(W1hh[2 * r0 + 1] * s,  W1hh[2 * r1 + 1] * s);
        P1b[p]   = fpack(b1[r0] * s,            b1[r1] * s);
    }
    u64 P2wi0[4], P2wi1[4], P2wh0[4], P2wh1[4], P2b[4];
#pragma unroll
    for (int p = 0; p < 4; p++) {
        float s = (p == 2) ? 1.0f : 0.5f;
        int r0 = 2 * p, r1 = 2 * p + 1;
        P2wi0[p] = fpack(W2ih[2 * r0 + 0] * s * m10, W2ih[2 * r1 + 0] * s * m10);
        P2wi1[p] = fpack(W2ih[2 * r0 + 1] * s * m11, W2ih[2 * r1 + 1] * s * m11);
        P2wh0[p] = fpack(W2hh[2 * r0 + 0] * s,       W2hh[2 * r1 + 0] * s);
        P2wh1[p] = fpack(W2hh[2 * r0 + 1] * s,       W2hh[2 * r1 + 1] * s);
        P2b[p]   = fpack(b2[r0] * s,                 b2[r1] * s);
    }
    // layer3 (H=1): rows 0=i(.5) 1=f(.5) 2=g(1) 3=o(.5); pairs A=(i,f), B=(g,o)
    u64 P3wi0A = fpack(W3ih[0] * 0.5f * m20, W3ih[2] * 0.5f * m20);
    u64 P3wi1A = fpack(W3ih[1] * 0.5f * m21, W3ih[3] * 0.5f * m21);
    u64 P3whA  = fpack(W3hh[0] * 0.5f,       W3hh[1] * 0.5f);
    u64 P3bA   = fpack(b3[0] * 0.5f,         b3[1] * 0.5f);
    u64 P3wi0B = fpack(W3ih[4] * m20,        W3ih[6] * 0.5f * m20);
    u64 P3wi1B = fpack(W3ih[5] * m21,        W3ih[7] * 0.5f * m21);
    u64 P3whB  = fpack(W3hh[2],              W3hh[3] * 0.5f);
    u64 P3bB   = fpack(b3[2],                b3[3] * 0.5f);

    // ---- state ----
    float h10 = 0.f, h11 = 0.f;  u64 cp1 = fpack(0.f, 0.f);
    float h20 = 0.f, h21 = 0.f;  u64 cp2 = fpack(0.f, 0.f);
    float h3 = 0.f,  c3 = 0.f;

    auto step1 = [&](float xt) {
        u64 x2  = fpack(xt, xt);
        u64 h0b = fpack(h10, h10), h1b = fpack(h11, h11);
        u64 gI = ffma2(x2, P1wi[0], ffma2(h0b, P1wh0[0], ffma2(h1b, P1wh1[0], P1b[0])));
        u64 gF = ffma2(x2, P1wi[1], ffma2(h0b, P1wh0[1], ffma2(h1b, P1wh1[1], P1b[1])));
        u64 gG = ffma2(x2, P1wi[2], ffma2(h0b, P1wh0[2], ffma2(h1b, P1wh1[2], P1b[2])));
        u64 gO = ffma2(x2, P1wi[3], ffma2(h0b, P1wh0[3], ffma2(h1b, P1wh1[3], P1b[3])));
        float a0, a1;
        funpack(gI, a0, a1); u64 tI = fpack(ftanh(a0), ftanh(a1));
        funpack(gF, a0, a1); u64 tF = fpack(ftanh(a0), ftanh(a1));
        funpack(gG, a0, a1); u64 tG = fpack(ftanh(a0), ftanh(a1));
        funpack(gO, a0, a1); u64 tO = fpack(ftanh(a0), ftanh(a1));
        u64 iP = ffma2(tI, H2, H2);
        u64 fP = ffma2(tF, H2, H2);
        u64 oP = ffma2(tO, H2, H2);
        cp1 = ffma2(fP, cp1, fmul2(iP, tG));
        funpack(cp1, a0, a1);
        u64 tC = fpack(ftanh(a0), ftanh(a1));
        u64 hP = fmul2(oP, tC);
        funpack(hP, h10, h11);
    };

    auto step2 = [&](float a0s, float a1s) {   // a = raw h1 (m1 folded into P2wi*)
        u64 a0b = fpack(a0s, a0s), a1b = fpack(a1s, a1s);
        u64 h0b = fpack(h20, h20), h1b = fpack(h21, h21);
        u64 gI = ffma2(a0b, P2wi0[0], ffma2(a1b, P2wi1[0], ffma2(h0b, P2wh0[0], ffma2(h1b, P2wh1[0], P2b[0]))));
        u64 gF = ffma2(a0b, P2wi0[1], ffma2(a1b, P2wi1[1], ffma2(h0b, P2wh0[1], ffma2(h1b, P2wh1[1], P2b[1]))));
        u64 gG = ffma2(a0b, P2wi0[2], ffma2(a1b, P2wi1[2], ffma2(h0b, P2wh0[2], ffma2(h1b, P2wh1[2], P2b[2]))));
        u64 gO = ffma2(a0b, P2wi0[3], ffma2(a1b, P2wi1[3], ffma2(h0b, P2wh0[3], ffma2(h1b, P2wh1[3], P2b[3]))));
        float a0, a1;
        funpack(gI, a0, a1); u64 tI = fpack(ftanh(a0), ftanh(a1));
        funpack(gF, a0, a1); u64 tF = fpack(ftanh(a0), ftanh(a1));
        funpack(gG, a0, a1); u64 tG = fpack(ftanh(a0), ftanh(a1));
        funpack(gO, a0, a1); u64 tO = fpack(ftanh(a0), ftanh(a1));
        u64 iP = ffma2(tI, H2, H2);
        u64 fP = ffma2(tF, H2, H2);
        u64 oP = ffma2(tO, H2, H2);
        cp2 = ffma2(fP, cp2, fmul2(iP, tG));
        funpack(cp2, a0, a1);
        u64 tC = fpack(ftanh(a0), ftanh(a1));
        u64 hP = fmul2(oP, tC);
        funpack(hP, h20, h21);
    };

    auto step3 = [&](float a0s, float a1s) -> float {   // a = raw h2 (m2 folded)
        u64 a0b = fpack(a0s, a0s), a1b = fpack(a1s, a1s);
        u64 h3b = fpack(h3, h3);
        u64 gA = ffma2(a0b, P3wi0A, ffma2(a1b, P3wi1A, ffma2(h3b, P3whA, P3bA)));
        u64 gB = ffma2(a0b, P3wi0B, ffma2(a1b, P3wi1B, ffma2(h3b, P3whB, P3bB)));
        float vi, vf, vg, vo;
        funpack(gA, vi, vf);
        funpack(gB, vg, vo);
        float si = fmaf(ftanh(vi), 0.5f, 0.5f);
        float sf = fmaf(ftanh(vf), 0.5f, 0.5f);
        float tg = ftanh(vg);
        float so = fmaf(ftanh(vo), 0.5f, 0.5f);
        c3 = fmaf(sf, c3, si * tg);
        h3 = so * ftanh(c3);
        return h3 * m30;
    };

    const float* xp = x + b;
    float* op = out + b;
    const long long Bs = (long long)B;

    // ---- pipeline prologue ----
    step1(xp[0]);
    {
        float p0 = h10, p1 = h11;
        step1(xp[Bs]);
        step2(p0, p1);
    }

    // ---- steady state: u = 2 .. T-1; layer1(u), layer2(u-1), layer3(u-2) ----
    float xa = xp[2 * Bs], xb = xp[3 * Bs], xc = xp[4 * Bs], xd = xp[5 * Bs];

#define PIPE_SUB(XREG, OFF, ROFF)                                              \
    {                                                                          \
        float p10 = h10, p11 = h11, p20 = h20, p21 = h21;                      \
        float nx = ((u + (ROFF)) < T) ? xp[(long long)(u + (ROFF)) * Bs] : 0.f;\
        step1(XREG);                                                           \
        step2(p10, p11);                                                       \
        op[(long long)(u + (OFF) - 2) * Bs] = step3(p20, p21);                 \
        XREG = nx;                                                             \
    }

    int u = 2;
    for (; u + 3 < T; u += 4) {
        PIPE_SUB(xa, 0, 4)
        PIPE_SUB(xb, 1, 5)
        PIPE_SUB(xc, 2, 6)
        PIPE_SUB(xd, 3, 7)
    }
    for (; u < T; ++u) {
        float p10 = h10, p11 = h11, p20 = h20, p21 = h21;
        step1(xa);
        step2(p10, p11);
        op[(long long)(u - 2) * Bs] = step3(p20, p21);
        xa = xb; xb = xc; xc = xd;
    }
#undef PIPE_SUB

    // ---- epilogue ----
    {
        float p20 = h20, p21 = h21;        // h2(T-2)
        step2(h10, h11);                   // h2(T-1)
        op[(long long)(T - 2) * Bs] = step3(p20, p21);
    }
    op[(long long)(T - 1) * Bs] = step3(h20, h21);
}

extern "C" void kernel_launch(void* const* d_in, const int* in_sizes, int n_in,
                              void* d_out, int out_size)
{
    const float* x    = (const float*)d_in[0];
    const float* W1ih = (const float*)d_in[1];
    const float* W1hh = (const float*)d_in[2];
    const float* b1   = (const float*)d_in[3];
    const float* m1   = (const float*)d_in[4];
    const float* W2ih = (const float*)d_in[5];
    const float* W2hh = (const float*)d_in[6];
    const float* b2   = (const float*)d_in[7];
    const float* m2   = (const float*)d_in[8];
    const float* W3ih = (const float*)d_in[9];
    const float* W3hh = (const float*)d_in[10];
    const float* b3   = (const float*)d_in[11];
    const float* m3   = (const float*)d_in[12];

    int B = in_sizes[12];            // m3 is [B]
    int T = in_sizes[0] / B;         // x is [T, B, 1]

    int threads = 64;
    int blocks = (B + threads - 1) / threads;
    vdlstm_v2_kernel<<<blocks, threads>>>(x, W1ih, W1hh, b1, m1,
                                          W2ih, W2hh, b2, m2,
                                          W3ih, W3hh, b3, m3,
                                          (float*)d_out, T, B);
}